// round 12
// baseline (speedup 1.0000x reference)
#include <cuda_runtime.h>
#include <stdint.h>
#include <math.h>

#define THRESH 1e-4f
#define MAXBP  8192
#define BIGL   0x40000000

// ---- kA config ----
#define BLKA 256
#define CHA  15                     // odd stride -> conflict-free smem chain reads
#define WUP  24
#define TILE (BLKA*CHA)             // 3840
#define XN   (TILE + WUP + 32)      // 3896
#define SZN  (TILE + 32)            // 3872  (static smem ~31 KB)
// box-screen constants: TH^(1/6)*0.997 and TH^(1/5)*1.02
#define C6BOX 0.212742f
#define C5BOX 0.161659f

// ---- k4 config ----
#define KBLK  256
#define NT    512                   // steps per tile
#define HALO4 8
#define NIN   (NT + HALO4)          // 520 staged floats per array
#define SLOT(i) ((i) ^ (((i) >> 3) & 7))   // float4-slot swizzle (R8-verified)
#define BPSM  4                     // resident blocks per SM target
#define NSM   148

// Scratch (no allocations); zero-init first run, self-reset for graph replays.
__device__ int g_anom_n = 0;
__device__ int g_ticket = 0;
__device__ int g_anom_p[MAXBP];
__device__ int g_anom_l[MAXBP];
__device__ int g_K;
__device__ int g_P[MAXBP];
__device__ int g_Q[MAXBP];
__device__ float g_C[8];            // w2, w4_2, dt1, dt2, d2t1, d2t2

// ============================================================================
// kA: fused Z-scan + box-screened anomaly scan + orbit walk.
// ============================================================================
__global__ __launch_bounds__(BLKA) void kA(const float* __restrict__ X,
                                           const float* __restrict__ pr,
                                           float* __restrict__ Z, int T) {
    __shared__ float sCC[XN];
    __shared__ float sZ[SZN];
    __shared__ float sC[4];
    int nsteps = T - 1;
    int B = blockIdx.x * TILE;
    int tid = threadIdx.x;

    if (tid == 0) {                 // tanh(double) ONCE per block
        sC[0] = (float)tanh((double)pr[0]);
        sC[1] = (float)tanh((double)pr[1]);
        sC[2] = pr[2];
        sC[3] = pr[3];
    }
    __syncthreads();
    float w1 = sC[0], w2 = sC[1], w3 = sC[2], w4 = sC[3];
    float w4_2 = 2.0f * w4;

    for (int i = tid; i < XN; i += BLKA) {       // stage cc coalesced, 0-padded
        int t = B - WUP + i;
        float x = (t >= 0 && t < T) ? X[t] : 0.f;
        sCC[i] = fmaf(w3, x * x, w1 * x);
    }
    __syncthreads();

    // ---- phase 1: fixed-trip h chain (cc=0 pad keeps h exactly 0) ----
    {
        int base = tid * CHA;
        float h = 0.f;
#pragma unroll
        for (int j = 0; j < WUP; ++j) {
            float u = fmaf(w4, h, w2);
            h = fmaf(h, u, sCC[base + j]);
        }
        sZ[base] = h;
#pragma unroll
        for (int j = 0; j < CHA; ++j) {
            float u = fmaf(w4, h, w2);
            h = fmaf(h, u, sCC[base + WUP + j]);
            sZ[base + 1 + j] = h;
        }
        if (tid == BLKA - 1) {                   // 31-step halo
#pragma unroll
            for (int j = 0; j < 31; ++j) {
                float u = fmaf(w4, h, w2);
                h = fmaf(h, u, sCC[base + WUP + CHA + j]);
                sZ[base + CHA + 1 + j] = h;
            }
        }
    }
    __syncthreads();

    if (B == 0 && tid == 0) Z[0] = 0.f;          // coalesced Z writeout
    for (int i = tid; i < TILE; i += BLKA) {
        int g = B + 1 + i;
        if (g <= nsteps) Z[g] = sZ[1 + i];
    }

    // ---- phase 2: box-screened anomaly scan ----
    float HHI, HLO;
    if (w4_2 > 0.f) { HHI = (C6BOX - w2) / w4_2; HLO = (C5BOX - w2) / w4_2; }
    else            { HHI = -1e30f; HLO = 1e30f; }
    int si = B + tid * CHA;
    if (si < nsteps) {
        int pe = si + CHA; if (pe > nsteps) pe = nsteps;
        int m = 0;
#pragma unroll
        for (int j = 0; j < 5; ++j) {
            float hv = sZ[si - B + j];
            m = (m >> 1) | ((hv > HLO && hv < HHI) ? 16 : 0);
        }
        for (int p = si; p < pe; ++p) {
            float hv = sZ[p - B + 5];
            m |= (hv > HLO && hv < HHI) ? 32 : 0;
            if (!(m == 63 && p + 6 <= nsteps)) {
                float d = 1.f; int l = -1;       // exact rare path
#pragma unroll 1
                for (int j = 0; j < 32; ++j) {
                    int t = p + j;
                    if (t >= nsteps) break;
                    float hh = sZ[t - B];
                    float a = __fadd_rn(w2, __fmul_rn(w4_2, hh));
                    d = __fmul_rn(d, fabsf(a));
                    if (d < THRESH) { l = j + 1; break; }
                }
                if (l != 6) {
                    int i = atomicAdd(&g_anom_n, 1);
                    if (i < MAXBP) { g_anom_p[i] = p; g_anom_l[i] = (l < 0) ? BIGL : l; }
                }
            }
            m >>= 1;
        }
    }
    __threadfence();
    __syncthreads();

    if (tid == 0) {                              // phase 3: orbit walk
        int tk = atomicAdd(&g_ticket, 1);
        if (tk == (int)gridDim.x - 1) {
            __threadfence();
            int n = g_anom_n; if (n > MAXBP) n = MAXBP;
            for (int i = 1; i < n; ++i) {
                int p = g_anom_p[i], ll = g_anom_l[i], j = i - 1;
                while (j >= 0 && g_anom_p[j] > p) {
                    g_anom_p[j + 1] = g_anom_p[j]; g_anom_l[j + 1] = g_anom_l[j]; --j;
                }
                g_anom_p[j + 1] = p; g_anom_l[j + 1] = ll;
            }
            int pos = 0, K = 0;
            for (int i = 0; i < n && K < MAXBP; ++i) {
                int p = g_anom_p[i];
                if (p < pos) continue;
                if ((p - pos) % 6 != 0) continue;
                int ll = g_anom_l[i];
                g_P[K] = p;
                if (ll >= BIGL) { g_Q[K] = 0x7fffffff; ++K; break; }
                g_Q[K] = p + ll; pos = p + ll; ++K;
            }
            g_K = K;
            g_anom_n = 0;
            g_ticket = 0;
            g_C[0] = w2; g_C[1] = w4_2;
            g_C[2] = 1.f - w1 * w1;
            g_C[3] = 1.f - w2 * w2;
            g_C[4] = -2.f * w1 * (1.f - w1 * w1);
            g_C[5] = -2.f * w2 * (1.f - w2 * w2);
        }
    }
}

// window [ws, we] containing step s.
__device__ __forceinline__ void wse(int s, int& ws, int& we) {
    int K = g_K;
    if (K == 0 || s < g_P[0]) { ws = s - s % 6; we = ws + 5; return; }
    int lo = 0, hi = K - 1;
    while (lo < hi) {
        int mid = (lo + hi + 1) >> 1;
        if (g_P[mid] <= s) lo = mid; else hi = mid - 1;
    }
    int q = g_Q[lo];
    if (s < q) { ws = g_P[lo]; we = q - 1; return; }
    int r = s - q;
    ws = q + (r - r % 6); we = ws + 5;
}

#define JH_STEP(x, h, a)                                              \
    do {                                                              \
        float g3 = 2.f * (h);                                         \
        H00 = fmaf((a), H00, (x) * d2t1);                             \
        H01 = fmaf((a), H01, dt2 * J0);                               \
        H02 = (a) * H02;                                              \
        H03 = fmaf((a), H03, g3 * J0);                                \
        H11 = fmaf((a), H11, fmaf(2.f * dt2, J1, (h) * d2t2));        \
        H12 = fmaf((a), H12, dt2 * J2);                               \
        H13 = fmaf((a), H13, fmaf(dt2, J3, g3 * J1));                 \
        H22 = (a) * H22;                                              \
        H23 = fmaf((a), H23, g3 * J2);                                \
        H33 = fmaf((a), H33, (2.f * g3) * J3);                        \
        J0 = fmaf((a), J0, (x) * dt1);                                \
        J1 = fmaf((a), J1, (h) * dt2);                                \
        J2 = fmaf((a), J2, (x) * (x));                                \
        J3 = fmaf((a), J3, (h) * (h));                                \
    } while (0)

#define STAGE_JH(lt)                                                   \
    do {                                                               \
        sJ4[lt] = make_float4(J0, J1, J2, J3);                         \
        int i0 = (lt) * 4;                                             \
        sH4[SLOT(i0 + 0)] = make_float4(H00, H01, H02, H03);           \
        sH4[SLOT(i0 + 1)] = make_float4(H01, H11, H12, H13);           \
        sH4[SLOT(i0 + 2)] = make_float4(H02, H12, H22, H23);           \
        sH4[SLOT(i0 + 3)] = make_float4(H03, H13, H23, H33);           \
    } while (0)

__device__ __forceinline__ void cpa16(unsigned int saddr, const float* g) {
    asm volatile("cp.async.ca.shared.global [%0], [%1], 16;" :: "r"(saddr), "l"(g));
}
#define CPA_COMMIT() asm volatile("cp.async.commit_group;")
#define CPA_WAIT1()  asm volatile("cp.async.wait_group 1;")

// ============================================================================
// k4: persistent blocks, double-buffered cp.async input, SPT=2 compute (R8),
// SLOT-swizzled H staging -> coalesced streams.
// ============================================================================
__global__ __launch_bounds__(KBLK, BPSM) void k4_main(const float* __restrict__ X,
                                                      const float* __restrict__ Z,
                                                      float* __restrict__ outJ,
                                                      float* __restrict__ outH,
                                                      int T, int ntiles) {
    extern __shared__ float sm[];
    // layout: sX0[NIN] sZ0[NIN] sX1[NIN] sZ1[NIN] sJ4[NT] sH4[NT*4]
    float*  sXb[2] = { sm,            sm + 2 * NIN };
    float*  sZb[2] = { sm + NIN,      sm + 3 * NIN };
    float4* sJ4 = (float4*)(sm + 4 * NIN);
    float4* sH4 = sJ4 + NT;
    int nsteps = T - 1;
    int tid = threadIdx.x;

    unsigned int smembase;
    asm("{ .reg .u64 t; cvta.to.shared.u64 t, %1; cvt.u32.u64 %0, t; }"
        : "=r"(smembase) : "l"(sm));

    if (blockIdx.x == 0 && tid == 0) {           // row 0 of J and H = 0
        ((float4*)outJ)[0] = make_float4(0, 0, 0, 0);
        float4 z4 = make_float4(0, 0, 0, 0);
        ((float4*)outH)[0] = z4; ((float4*)outH)[1] = z4;
        ((float4*)outH)[2] = z4; ((float4*)outH)[3] = z4;
    }

    // async-stage one tile's X/Z (130 16B chunks per array)
    auto preload = [&](int tile, int buf) {
        int nch = NIN / 4;                       // 130
        for (int c = tid; c < 2 * nch; c += KBLK) {
            int arr = c >= nch;                  // 0 = X, 1 = Z
            int ch  = arr ? c - nch : c;
            int g0  = tile * NT - HALO4 + 4 * ch;
            unsigned int dst = smembase +
                (unsigned int)(((arr ? sZb[buf] : sXb[buf]) - sm) + 4 * ch) * 4u;
            if (g0 >= 0) {
                cpa16(dst, (arr ? Z : X) + g0);
            } else {                             // tile 0 leading pad
                asm volatile("st.shared.v4.b32 [%0], {%1,%1,%1,%1};"
                             :: "r"(dst), "r"(0) : "memory");
            }
        }
    };

    int tile = blockIdx.x;
    int cur = 0;
    if (tile < ntiles) preload(tile, 0);
    CPA_COMMIT();

    for (; tile < ntiles; tile += gridDim.x) {
        int nxt = tile + gridDim.x;
        if (nxt < ntiles) preload(nxt, cur ^ 1);
        CPA_COMMIT();
        CPA_WAIT1();
        __syncthreads();

        const float* sX4 = sXb[cur];
        const float* sZ4 = sZb[cur];
        int s0 = tile * NT;
        int s  = s0 + tid * 2;
        if (s < nsteps) {
            float w2   = g_C[0], w4_2 = g_C[1];
            float dt1  = g_C[2], dt2  = g_C[3];
            float d2t1 = g_C[4], d2t2 = g_C[5];

            int ws, we; wse(s, ws, we);

            float J0 = 0, J1 = 0, J2 = 0, J3 = 0;
            float H00 = 0, H01 = 0, H02 = 0, H03 = 0, H11 = 0;
            float H12 = 0, H13 = 0, H22 = 0, H23 = 0, H33 = 0;

            int lbase = tid * 2 + HALO4;
            if (ws >= s - 5) {
                int jmin = ws - (s - 5);         // 0..5
#pragma unroll
                for (int j = 0; j < 6; ++j) {
                    int li = lbase - 5 + j;      // >= 3, always in-range
                    float msk = (j >= jmin) ? 1.f : 0.f;
                    float x = sX4[li] * msk;
                    float h = sZ4[li] * msk;
                    float a = __fadd_rn(w2, __fmul_rn(w4_2, h));
                    JH_STEP(x, h, a);
                }
            } else {
#pragma unroll 1
                for (int t = ws; t <= s; ++t) {  // rare long window
                    int li = t - s0 + HALO4;
                    float x, h;
                    if (li >= 0) { x = sX4[li]; h = sZ4[li]; }
                    else         { x = X[t];    h = Z[t];   }
                    float a = __fadd_rn(w2, __fmul_rn(w4_2, h));
                    JH_STEP(x, h, a);
                }
            }

            float keep = (s == we) ? 0.f : 1.f;
            J0 *= keep; J1 *= keep; J2 *= keep; J3 *= keep;
            H00 *= keep; H01 *= keep; H02 *= keep; H03 *= keep; H11 *= keep;
            H12 *= keep; H13 *= keep; H22 *= keep; H23 *= keep; H33 *= keep;
            STAGE_JH(tid * 2);

            if (s + 1 < nsteps) {                // second step on post-reset carry
                float x = sX4[lbase + 1], h = sZ4[lbase + 1];
                float a = __fadd_rn(w2, __fmul_rn(w4_2, h));
                JH_STEP(x, h, a);
                int ws2, we2; wse(s + 1, ws2, we2);
                float keep2 = (s + 1 == we2) ? 0.f : 1.f;
                J0 *= keep2; J1 *= keep2; J2 *= keep2; J3 *= keep2;
                H00 *= keep2; H01 *= keep2; H02 *= keep2; H03 *= keep2;
                H11 *= keep2; H12 *= keep2; H13 *= keep2; H22 *= keep2;
                H23 *= keep2; H33 *= keep2;
                STAGE_JH(tid * 2 + 1);
            }
        }
        __syncthreads();

        int cnt = nsteps - s0; if (cnt > NT) cnt = NT;
        if (cnt < 0) cnt = 0;
        float4* Jout = (float4*)outJ + (size_t)(s0 + 1);
#pragma unroll
        for (int k = 0; k < 2; ++k) {            // coalesced J stream
            int i = tid + k * KBLK;
            if (i < cnt) Jout[i] = sJ4[i];
        }
        float4* Hout = (float4*)outH + (size_t)(s0 + 1) * 4;
#pragma unroll
        for (int k = 0; k < 8; ++k) {            // coalesced H stream
            int i = tid + k * KBLK;
            if (i < cnt * 4) Hout[i] = sH4[SLOT(i)];
        }
        cur ^= 1;
        __syncthreads();                         // sJ4/sH4 reuse protection
    }
}

extern "C" void kernel_launch(void* const* d_in, const int* in_sizes, int n_in,
                              void* d_out, int out_size) {
    const float* X  = (const float*)d_in[0];
    const float* pr = (const float*)d_in[1];
    int T = in_sizes[0];
    float* out = (float*)d_out;
    float* Z = out;                        // [T]
    float* J = out + (size_t)T;            // [T,4]
    float* H = out + (size_t)5 * T;        // [T,4,4]

    const int SMEMB = (4 * NIN + NT * 4 + NT * 16) * (int)sizeof(float);
    static bool configured = false;
    if (!configured) {
        cudaFuncSetAttribute(k4_main, cudaFuncAttributeMaxDynamicSharedMemorySize, SMEMB);
        configured = true;
    }

    int nsteps = T - 1;
    int gA = (nsteps + TILE - 1) / TILE;
    kA<<<gA, BLKA>>>(X, pr, Z, T);
    int ntiles = (nsteps + NT - 1) / NT;
    int gB = BPSM * NSM; if (gB > ntiles) gB = ntiles;
    k4_main<<<gB, KBLK, SMEMB>>>(X, Z, J, H, T, ntiles);
}

// round 13
// speedup vs baseline: 1.0982x; 1.0982x over previous
#include <cuda_runtime.h>
#include <stdint.h>
#include <math.h>

#define THRESH 1e-4f
#define MAXBP  8192
#define BIGL   0x40000000

// ---- kA config ----
#define BLKA 256
#define CHA  9                      // odd stride -> conflict-free smem chain reads
#define WUP  24
#define TILE (BLKA*CHA)             // 2304
#define XN   (TILE + WUP + 32)      // 2360
#define SZN  (TILE + 32)            // 2336
// box-screen constants: TH^(1/6)*0.997 and TH^(1/5)*1.02
#define C6BOX 0.212742f
#define C5BOX 0.161659f

// ---- k4 config ----
#define KBLK  256
#define OPT   3                     // outputs per thread; NBK divisible by 6
#define NBK   (KBLK*OPT)            // 768
#define HALO4 8
#define SLOT(i) ((i) ^ (((i) >> 3) & 7))   // float4-slot swizzle (verified)

// Scratch (no allocations); zero-init first run, self-reset for graph replays.
__device__ int g_anom_n = 0;
__device__ int g_ticket = 0;
__device__ int g_anom_p[MAXBP];
__device__ int g_anom_l[MAXBP];
__device__ int g_K;
__device__ int g_P[MAXBP];
__device__ int g_Q[MAXBP];
__device__ float g_C[8];            // w2, w4_2, dt1, dt2, d2t1, d2t2

// ============================================================================
// kA: fused Z-scan + box-screened anomaly scan + orbit walk.
// ============================================================================
__global__ __launch_bounds__(BLKA) void kA(const float* __restrict__ X,
                                           const float* __restrict__ pr,
                                           float* __restrict__ Z, int T) {
    __shared__ float sCC[XN];
    __shared__ float sZ[SZN];
    __shared__ float sC[4];
    int nsteps = T - 1;
    int B = blockIdx.x * TILE;
    int tid = threadIdx.x;

    if (tid == 0) {                 // tanh(double) ONCE per block
        sC[0] = (float)tanh((double)pr[0]);
        sC[1] = (float)tanh((double)pr[1]);
        sC[2] = pr[2];
        sC[3] = pr[3];
    }
    __syncthreads();
    float w1 = sC[0], w2 = sC[1], w3 = sC[2], w4 = sC[3];
    float w4_2 = 2.0f * w4;

    for (int i = tid; i < XN; i += BLKA) {       // stage cc coalesced, 0-padded
        int t = B - WUP + i;
        float x = (t >= 0 && t < T) ? X[t] : 0.f;
        sCC[i] = fmaf(w3, x * x, w1 * x);
    }
    __syncthreads();

    // ---- phase 1: fixed-trip h chain (cc=0 pad keeps h exactly 0) ----
    {
        int base = tid * CHA;
        float h = 0.f;
#pragma unroll
        for (int j = 0; j < WUP; ++j) {
            float u = fmaf(w4, h, w2);
            h = fmaf(h, u, sCC[base + j]);
        }
        sZ[base] = h;
#pragma unroll
        for (int j = 0; j < CHA; ++j) {
            float u = fmaf(w4, h, w2);
            h = fmaf(h, u, sCC[base + WUP + j]);
            sZ[base + 1 + j] = h;
        }
        if (tid == BLKA - 1) {                   // 31-step halo
#pragma unroll
            for (int j = 0; j < 31; ++j) {
                float u = fmaf(w4, h, w2);
                h = fmaf(h, u, sCC[base + WUP + CHA + j]);
                sZ[base + CHA + 1 + j] = h;
            }
        }
    }
    __syncthreads();

    if (B == 0 && tid == 0) Z[0] = 0.f;          // coalesced Z writeout
    for (int i = tid; i < TILE; i += BLKA) {
        int g = B + 1 + i;
        if (g <= nsteps) Z[g] = sZ[1 + i];
    }

    // ---- phase 2: box-screened anomaly scan ----
    float HHI, HLO;
    if (w4_2 > 0.f) { HHI = (C6BOX - w2) / w4_2; HLO = (C5BOX - w2) / w4_2; }
    else            { HHI = -1e30f; HLO = 1e30f; }
    int si = B + tid * CHA;
    if (si < nsteps) {
        int pe = si + CHA; if (pe > nsteps) pe = nsteps;
        int m = 0;
#pragma unroll
        for (int j = 0; j < 5; ++j) {
            float hv = sZ[si - B + j];
            m = (m >> 1) | ((hv > HLO && hv < HHI) ? 16 : 0);
        }
        for (int p = si; p < pe; ++p) {
            float hv = sZ[p - B + 5];
            m |= (hv > HLO && hv < HHI) ? 32 : 0;
            if (!(m == 63 && p + 6 <= nsteps)) {
                float d = 1.f; int l = -1;       // exact rare path
#pragma unroll 1
                for (int j = 0; j < 32; ++j) {
                    int t = p + j;
                    if (t >= nsteps) break;
                    float hh = sZ[t - B];
                    float a = __fadd_rn(w2, __fmul_rn(w4_2, hh));
                    d = __fmul_rn(d, fabsf(a));
                    if (d < THRESH) { l = j + 1; break; }
                }
                if (l != 6) {
                    int i = atomicAdd(&g_anom_n, 1);
                    if (i < MAXBP) { g_anom_p[i] = p; g_anom_l[i] = (l < 0) ? BIGL : l; }
                }
            }
            m >>= 1;
        }
    }
    __threadfence();
    __syncthreads();

    if (tid == 0) {                              // phase 3: orbit walk
        int tk = atomicAdd(&g_ticket, 1);
        if (tk == (int)gridDim.x - 1) {
            __threadfence();
            int n = g_anom_n; if (n > MAXBP) n = MAXBP;
            for (int i = 1; i < n; ++i) {
                int p = g_anom_p[i], ll = g_anom_l[i], j = i - 1;
                while (j >= 0 && g_anom_p[j] > p) {
                    g_anom_p[j + 1] = g_anom_p[j]; g_anom_l[j + 1] = g_anom_l[j]; --j;
                }
                g_anom_p[j + 1] = p; g_anom_l[j + 1] = ll;
            }
            int pos = 0, K = 0;
            for (int i = 0; i < n && K < MAXBP; ++i) {
                int p = g_anom_p[i];
                if (p < pos) continue;
                if ((p - pos) % 6 != 0) continue;
                int ll = g_anom_l[i];
                g_P[K] = p;
                if (ll >= BIGL) { g_Q[K] = 0x7fffffff; ++K; break; }
                g_Q[K] = p + ll; pos = p + ll; ++K;
            }
            g_K = K;
            g_anom_n = 0;
            g_ticket = 0;
            g_C[0] = w2; g_C[1] = w4_2;
            g_C[2] = 1.f - w1 * w1;
            g_C[3] = 1.f - w2 * w2;
            g_C[4] = -2.f * w1 * (1.f - w1 * w1);
            g_C[5] = -2.f * w2 * (1.f - w2 * w2);
        }
    }
}

// window [ws, we] containing step s.
__device__ __forceinline__ void wse(int s, int& ws, int& we) {
    int K = g_K;
    if (K == 0 || s < g_P[0]) { ws = s - s % 6; we = ws + 5; return; }
    int lo = 0, hi = K - 1;
    while (lo < hi) {
        int mid = (lo + hi + 1) >> 1;
        if (g_P[mid] <= s) lo = mid; else hi = mid - 1;
    }
    int q = g_Q[lo];
    if (s < q) { ws = g_P[lo]; we = q - 1; return; }
    int r = s - q;
    ws = q + (r - r % 6); we = ws + 5;
}

#define JH_STEP(x, h, a)                                              \
    do {                                                              \
        float g3 = 2.f * (h);                                         \
        H00 = fmaf((a), H00, (x) * d2t1);                             \
        H01 = fmaf((a), H01, dt2 * J0);                               \
        H02 = (a) * H02;                                              \
        H03 = fmaf((a), H03, g3 * J0);                                \
        H11 = fmaf((a), H11, fmaf(2.f * dt2, J1, (h) * d2t2));        \
        H12 = fmaf((a), H12, dt2 * J2);                               \
        H13 = fmaf((a), H13, fmaf(dt2, J3, g3 * J1));                 \
        H22 = (a) * H22;                                              \
        H23 = fmaf((a), H23, g3 * J2);                                \
        H33 = fmaf((a), H33, (2.f * g3) * J3);                        \
        J0 = fmaf((a), J0, (x) * dt1);                                \
        J1 = fmaf((a), J1, (h) * dt2);                                \
        J2 = fmaf((a), J2, (x) * (x));                                \
        J3 = fmaf((a), J3, (h) * (h));                                \
    } while (0)

// ============================================================================
// k4: window-aligned OPT=3 (even-phase threads need NO rebuild; odd-phase
// rebuild exactly 3); SLOT-swizzled smem staging -> coalesced streams.
// ============================================================================
__global__ __launch_bounds__(KBLK) void k4_main(const float* __restrict__ X,
                                                const float* __restrict__ Z,
                                                float* __restrict__ outJ,
                                                float* __restrict__ outH, int T) {
    extern __shared__ float sm[];
    float*  sX4 = sm;                            // NBK+HALO4
    float*  sZ4 = sm + (NBK + HALO4);            // NBK+HALO4
    float4* sJ4 = (float4*)(sm + 2 * (NBK + HALO4));
    float4* sH4 = sJ4 + NBK;
    int nsteps = T - 1;
    int s0 = blockIdx.x * NBK;
    int tid = threadIdx.x;

    if (blockIdx.x == 0 && tid == 0) {           // row 0 of J and H = 0
        ((float4*)outJ)[0] = make_float4(0, 0, 0, 0);
        float4 z4 = make_float4(0, 0, 0, 0);
        ((float4*)outH)[0] = z4; ((float4*)outH)[1] = z4;
        ((float4*)outH)[2] = z4; ((float4*)outH)[3] = z4;
    }

    for (int i = tid; i < NBK + HALO4; i += KBLK) {   // stage X/Z coalesced
        int t = s0 - HALO4 + i;
        float xv = 0.f, hv = 0.f;
        if (t >= 0 && t < nsteps) { xv = X[t]; hv = Z[t]; }
        sX4[i] = xv; sZ4[i] = hv;
    }
    __syncthreads();

    int s = s0 + tid * OPT;
    if (s < nsteps) {
        float w2   = g_C[0], w4_2 = g_C[1];
        float dt1  = g_C[2], dt2  = g_C[3];
        float d2t1 = g_C[4], d2t2 = g_C[5];

        int ws, we; wse(s, ws, we);

        float J0 = 0, J1 = 0, J2 = 0, J3 = 0;
        float H00 = 0, H01 = 0, H02 = 0, H03 = 0, H11 = 0;
        float H12 = 0, H13 = 0, H22 = 0, H23 = 0, H33 = 0;

        // ---- pre-roll: bring carry to just before step s ----
        if (ws < s) {
            if (ws >= s - 5) {
                // common case: <=5 steps, all inside staged range (li >= 3)
#pragma unroll 1
                for (int t = ws; t < s; ++t) {
                    int li = t - s0 + HALO4;
                    float x = sX4[li], h = sZ4[li];
                    float a = __fadd_rn(w2, __fmul_rn(w4_2, h));
                    JH_STEP(x, h, a);
                }
            } else {
                // pathological long window
#pragma unroll 1
                for (int t = ws; t < s; ++t) {
                    int li = t - s0 + HALO4;
                    float x, h;
                    if (li >= 0) { x = sX4[li]; h = sZ4[li]; }
                    else         { x = X[t];    h = Z[t];   }
                    float a = __fadd_rn(w2, __fmul_rn(w4_2, h));
                    JH_STEP(x, h, a);
                }
            }
        }

        // ---- emit OPT adjacent outputs ----
#pragma unroll
        for (int k = 0; k < OPT; ++k) {
            int t = s + k;
            if (t < nsteps) {
                int li = tid * OPT + k + HALO4;
                float x = sX4[li], h = sZ4[li];
                float a = __fadd_rn(w2, __fmul_rn(w4_2, h));
                JH_STEP(x, h, a);
                float keep = (t == we) ? 0.f : 1.f;
                J0 *= keep; J1 *= keep; J2 *= keep; J3 *= keep;
                H00 *= keep; H01 *= keep; H02 *= keep; H03 *= keep;
                H11 *= keep; H12 *= keep; H13 *= keep; H22 *= keep;
                H23 *= keep; H33 *= keep;
                int lt = tid * OPT + k;
                sJ4[lt] = make_float4(J0, J1, J2, J3);
                int i0 = lt * 4;
                sH4[SLOT(i0 + 0)] = make_float4(H00, H01, H02, H03);
                sH4[SLOT(i0 + 1)] = make_float4(H01, H11, H12, H13);
                sH4[SLOT(i0 + 2)] = make_float4(H02, H12, H22, H23);
                sH4[SLOT(i0 + 3)] = make_float4(H03, H13, H23, H33);
                // window crossing (rare: normal phases end exactly at k==OPT-1)
                if (t == we && k + 1 < OPT && t + 1 < nsteps) {
                    wse(t + 1, ws, we);
                }
            }
        }
    }
    __syncthreads();

    int cnt = nsteps - s0; if (cnt > NBK) cnt = NBK;
    if (cnt < 0) cnt = 0;
    float4* Jout = (float4*)outJ + (size_t)(s0 + 1);
#pragma unroll
    for (int k = 0; k < OPT; ++k) {              // coalesced J stream
        int i = tid + k * KBLK;
        if (i < cnt) Jout[i] = sJ4[i];
    }
    float4* Hout = (float4*)outH + (size_t)(s0 + 1) * 4;
#pragma unroll
    for (int k = 0; k < 4 * OPT; ++k) {          // coalesced H stream
        int i = tid + k * KBLK;
        if (i < cnt * 4) Hout[i] = sH4[SLOT(i)];
    }
}

extern "C" void kernel_launch(void* const* d_in, const int* in_sizes, int n_in,
                              void* d_out, int out_size) {
    const float* X  = (const float*)d_in[0];
    const float* pr = (const float*)d_in[1];
    int T = in_sizes[0];
    float* out = (float*)d_out;
    float* Z = out;                        // [T]
    float* J = out + (size_t)T;            // [T,4]
    float* H = out + (size_t)5 * T;        // [T,4,4]

    const int SMEMB = (2 * (NBK + HALO4) + NBK * 4 + NBK * 16) * (int)sizeof(float);
    static bool configured = false;
    if (!configured) {
        cudaFuncSetAttribute(k4_main, cudaFuncAttributeMaxDynamicSharedMemorySize, SMEMB);
        configured = true;
    }

    int nsteps = T - 1;
    int gA = (nsteps + TILE - 1) / TILE;
    kA<<<gA, BLKA>>>(X, pr, Z, T);
    int gB = (nsteps + NBK - 1) / NBK;
    k4_main<<<gB, KBLK, SMEMB>>>(X, Z, J, H, T);
}